// round 1
// baseline (speedup 1.0000x reference)
#include <cuda_runtime.h>
#include <cuda_bf16.h>

// ---------------------------------------------------------------------------
// RelationalKENN
//   up = u + scatter(du1 @ index1) + scatter(du2 @ index2),  u = unary + unary-enhance
//   bp = binary + db
// Binary clauses only touch columns 0..3 of u, so we stash those 4 columns per
// node in a device scratch (L2-resident, 1.6 MB) for the edge pass.
// ---------------------------------------------------------------------------

#define MAX_NODES 100000

__device__ float g_u4[MAX_NODES * 4];   // u columns 0..3, packed per node

__global__ void unary_kernel(const float* __restrict__ unary,
                             const float* __restrict__ uw,
                             float* __restrict__ up_out,
                             int n_nodes)
{
    int node = blockIdx.x * blockDim.x + threadIdx.x;
    if (node >= n_nodes) return;

    const float4* p = reinterpret_cast<const float4*>(unary + (size_t)node * 16);
    float4 a = p[0], b4 = p[1], c4 = p[2], d4 = p[3];
    float x[16] = {a.x, a.y, a.z, a.w,  b4.x, b4.y, b4.z, b4.w,
                   c4.x, c4.y, c4.z, c4.w, d4.x, d4.y, d4.z, d4.w};

    float del[16];
#pragma unroll
    for (int i = 0; i < 16; i++) del[i] = 0.f;

    // 2-literal clause, signs [-1, +1]
    auto clause2 = [&](int ia, int ib, float w) {
        // softmax([-x_a, x_b]): weight on literal b = sigmoid(x_a + x_b)
        float s1 = 1.f / (1.f + __expf(-(x[ia] + x[ib])));
        float s0 = 1.f - s1;
        del[ia] -= w * s0;
        del[ib] += w * s1;
    };
    // 3-literal clause, signs [-1, +1, +1]
    auto clause3 = [&](int ia, int ib, int ic, float w) {
        float v0 = -x[ia], v1 = x[ib], v2 = x[ic];
        float m  = fmaxf(v0, fmaxf(v1, v2));
        float e0 = __expf(v0 - m), e1 = __expf(v1 - m), e2 = __expf(v2 - m);
        float inv = w / (e0 + e1 + e2);
        del[ia] -= inv * e0;
        del[ib] += inv * e1;
        del[ic] += inv * e2;
    };

    clause2(0, 1,      uw[0]);
    clause2(1, 2,      uw[1]);
    clause3(2, 3, 4,   uw[2]);
    clause2(4, 5,      uw[3]);
    clause3(6, 7, 8,   uw[4]);
    clause2(8, 9,      uw[5]);
    clause3(10, 11, 12, uw[6]);
    clause3(13, 14, 15, uw[7]);

    float u[16];
#pragma unroll
    for (int i = 0; i < 16; i++) u[i] = x[i] + del[i];

    float4* o = reinterpret_cast<float4*>(up_out + (size_t)node * 16);
    o[0] = make_float4(u[0],  u[1],  u[2],  u[3]);
    o[1] = make_float4(u[4],  u[5],  u[6],  u[7]);
    o[2] = make_float4(u[8],  u[9],  u[10], u[11]);
    o[3] = make_float4(u[12], u[13], u[14], u[15]);

    reinterpret_cast<float4*>(g_u4)[node] = make_float4(u[0], u[1], u[2], u[3]);
}

__global__ void binary_kernel(const float* __restrict__ binary,
                              const int* __restrict__ index1,
                              const int* __restrict__ index2,
                              const float* __restrict__ bw,
                              float* __restrict__ up_out,
                              float* __restrict__ bp_out,
                              int n_edges)
{
    int e = blockIdx.x * blockDim.x + threadIdx.x;
    if (e >= n_edges) return;

    int i1 = index1[e];
    int i2 = index2[e];

    float4 bv = reinterpret_cast<const float4*>(binary)[e];
    float4 u1 = reinterpret_cast<const float4*>(g_u4)[i1];
    float4 u2 = reinterpret_cast<const float4*>(g_u4)[i2];

    float b[4]  = {bv.x, bv.y, bv.z, bv.w};
    float a1[4] = {u1.x, u1.y, u1.z, u1.w};
    float a2[4] = {u2.x, u2.y, u2.z, u2.w};
    float wv[4] = {bw[0], bw[1], bw[2], bw[3]};

    float bpv[4];
    float* up1 = up_out + (size_t)i1 * 16;
    float* up2 = up_out + (size_t)i2 * 16;

#pragma unroll
    for (int i = 0; i < 4; i++) {
        // clause i: sel = [-u1[i], -binary[i], +u2[i]], signs [-1,-1,+1]
        float v0 = -a1[i], v1 = -b[i], v2 = a2[i];
        float m  = fmaxf(v0, fmaxf(v1, v2));
        float e0 = __expf(v0 - m), e1 = __expf(v1 - m), e2 = __expf(v2 - m);
        float inv = wv[i] / (e0 + e1 + e2);
        float du1 = -inv * e0;
        float db  = -inv * e1;
        float du2 =  inv * e2;

        atomicAdd(up1 + i, du1);
        atomicAdd(up2 + i, du2);
        bpv[i] = b[i] + db;
    }

    reinterpret_cast<float4*>(bp_out)[e] = make_float4(bpv[0], bpv[1], bpv[2], bpv[3]);
}

extern "C" void kernel_launch(void* const* d_in, const int* in_sizes, int n_in,
                              void* d_out, int out_size)
{
    const float* unary   = (const float*)d_in[0];
    const float* binary  = (const float*)d_in[1];
    const int*   index1  = (const int*)d_in[2];
    const int*   index2  = (const int*)d_in[3];
    const float* uw      = (const float*)d_in[4];
    const float* bw      = (const float*)d_in[5];

    int n_nodes = in_sizes[0] / 16;
    int n_edges = in_sizes[1] / 4;

    float* up = (float*)d_out;
    float* bp = up + (size_t)n_nodes * 16;

    unary_kernel<<<(n_nodes + 255) / 256, 256>>>(unary, uw, up, n_nodes);
    binary_kernel<<<(n_edges + 255) / 256, 256>>>(binary, index1, index2, bw,
                                                  up, bp, n_edges);
}

// round 2
// speedup vs baseline: 2.0804x; 2.0804x over previous
#include <cuda_runtime.h>
#include <cuda_bf16.h>

// ---------------------------------------------------------------------------
// RelationalKENN
//   up = u + scatter(du1 @ index1) + scatter(du2 @ index2),  u = unary + enhance
//   bp = binary + db
// Binary clauses only touch columns 0..3 of u -> stash them in a 1.6 MB
// L2-resident scratch. Scatter-adds use red.global.add.v4.f32 (one REDG.128
// per node-update instead of 4 scalar REDG.32).
// ---------------------------------------------------------------------------

#define MAX_NODES 100000

__device__ float g_u4[MAX_NODES * 4];   // u columns 0..3, packed per node

__global__ void unary_kernel(const float* __restrict__ unary,
                             const float* __restrict__ uw,
                             float* __restrict__ up_out,
                             int n_nodes)
{
    int node = blockIdx.x * blockDim.x + threadIdx.x;
    if (node >= n_nodes) return;

    const float4* p = reinterpret_cast<const float4*>(unary + (size_t)node * 16);
    float4 a = p[0], b4 = p[1], c4 = p[2], d4 = p[3];
    float x[16] = {a.x, a.y, a.z, a.w,  b4.x, b4.y, b4.z, b4.w,
                   c4.x, c4.y, c4.z, c4.w, d4.x, d4.y, d4.z, d4.w};

    float del[16];
#pragma unroll
    for (int i = 0; i < 16; i++) del[i] = 0.f;

    // 2-literal clause, signs [-1, +1]
    auto clause2 = [&](int ia, int ib, float w) {
        float s1 = 1.f / (1.f + __expf(-(x[ia] + x[ib])));
        float s0 = 1.f - s1;
        del[ia] -= w * s0;
        del[ib] += w * s1;
    };
    // 3-literal clause, signs [-1, +1, +1]
    auto clause3 = [&](int ia, int ib, int ic, float w) {
        float e0 = __expf(-x[ia]), e1 = __expf(x[ib]), e2 = __expf(x[ic]);
        float inv = w / (e0 + e1 + e2);
        del[ia] -= inv * e0;
        del[ib] += inv * e1;
        del[ic] += inv * e2;
    };

    clause2(0, 1,       __ldg(uw + 0));
    clause2(1, 2,       __ldg(uw + 1));
    clause3(2, 3, 4,    __ldg(uw + 2));
    clause2(4, 5,       __ldg(uw + 3));
    clause3(6, 7, 8,    __ldg(uw + 4));
    clause2(8, 9,       __ldg(uw + 5));
    clause3(10, 11, 12, __ldg(uw + 6));
    clause3(13, 14, 15, __ldg(uw + 7));

    float u[16];
#pragma unroll
    for (int i = 0; i < 16; i++) u[i] = x[i] + del[i];

    float4* o = reinterpret_cast<float4*>(up_out + (size_t)node * 16);
    o[0] = make_float4(u[0],  u[1],  u[2],  u[3]);
    o[1] = make_float4(u[4],  u[5],  u[6],  u[7]);
    o[2] = make_float4(u[8],  u[9],  u[10], u[11]);
    o[3] = make_float4(u[12], u[13], u[14], u[15]);

    reinterpret_cast<float4*>(g_u4)[node] = make_float4(u[0], u[1], u[2], u[3]);
}

__device__ __forceinline__ void red_add_v4(float* ptr, float a, float b,
                                           float c, float d)
{
    asm volatile("red.global.add.v4.f32 [%0], {%1, %2, %3, %4};"
                 :: "l"(ptr), "f"(a), "f"(b), "f"(c), "f"(d)
                 : "memory");
}

__global__ void binary_kernel(const float* __restrict__ binary,
                              const int* __restrict__ index1,
                              const int* __restrict__ index2,
                              const float* __restrict__ bw,
                              float* __restrict__ up_out,
                              float* __restrict__ bp_out,
                              int n_edges)
{
    int e = blockIdx.x * blockDim.x + threadIdx.x;
    if (e >= n_edges) return;

    int i1 = index1[e];
    int i2 = index2[e];

    float4 bv = reinterpret_cast<const float4*>(binary)[e];
    float4 u1 = reinterpret_cast<const float4*>(g_u4)[i1];
    float4 u2 = reinterpret_cast<const float4*>(g_u4)[i2];

    float b[4]  = {bv.x, bv.y, bv.z, bv.w};
    float a1[4] = {u1.x, u1.y, u1.z, u1.w};
    float a2[4] = {u2.x, u2.y, u2.z, u2.w};
    float wv[4] = {__ldg(bw + 0), __ldg(bw + 1), __ldg(bw + 2), __ldg(bw + 3)};

    float du1[4], du2[4], bpv[4];

#pragma unroll
    for (int i = 0; i < 4; i++) {
        // clause i: sel = [-u1[i], -binary[i], +u2[i]], signs [-1,-1,+1]
        // inputs are O(1); plain __expf is safe without max-subtraction.
        float e0 = __expf(-a1[i]), e1 = __expf(-b[i]), e2 = __expf(a2[i]);
        float inv = wv[i] / (e0 + e1 + e2);
        du1[i] = -inv * e0;
        du2[i] =  inv * e2;
        bpv[i] = b[i] - inv * e1;
    }

    red_add_v4(up_out + (size_t)i1 * 16, du1[0], du1[1], du1[2], du1[3]);
    red_add_v4(up_out + (size_t)i2 * 16, du2[0], du2[1], du2[2], du2[3]);

    reinterpret_cast<float4*>(bp_out)[e] = make_float4(bpv[0], bpv[1], bpv[2], bpv[3]);
}

extern "C" void kernel_launch(void* const* d_in, const int* in_sizes, int n_in,
                              void* d_out, int out_size)
{
    const float* unary   = (const float*)d_in[0];
    const float* binary  = (const float*)d_in[1];
    const int*   index1  = (const int*)d_in[2];
    const int*   index2  = (const int*)d_in[3];
    const float* uw      = (const float*)d_in[4];
    const float* bw      = (const float*)d_in[5];

    int n_nodes = in_sizes[0] / 16;
    int n_edges = in_sizes[1] / 4;

    float* up = (float*)d_out;
    float* bp = up + (size_t)n_nodes * 16;

    unary_kernel<<<(n_nodes + 255) / 256, 256>>>(unary, uw, up, n_nodes);
    binary_kernel<<<(n_edges + 255) / 256, 256>>>(binary, index1, index2, bw,
                                                  up, bp, n_edges);
}

// round 3
// speedup vs baseline: 2.0942x; 1.0066x over previous
#include <cuda_runtime.h>
#include <cuda_bf16.h>

// ---------------------------------------------------------------------------
// RelationalKENN
//   up = u + scatter(du1 @ index1) + scatter(du2 @ index2),  u = unary + enhance
//   bp = binary + db
// Binary clauses only touch columns 0..3 of u -> 1.6 MB L2-resident scratch.
// Scatter-adds are red.global.add.v4.f32. Edge pass: 2 edges/thread,
// block-strided for coalescing, gathers batched for MLP.
// ---------------------------------------------------------------------------

#define MAX_NODES 100000

__device__ float g_u4[MAX_NODES * 4];   // u columns 0..3, packed per node

__global__ void unary_kernel(const float* __restrict__ unary,
                             const float* __restrict__ uw,
                             float* __restrict__ up_out,
                             int n_nodes)
{
    int node = blockIdx.x * blockDim.x + threadIdx.x;
    if (node >= n_nodes) return;

    const float4* p = reinterpret_cast<const float4*>(unary + (size_t)node * 16);
    float4 a = p[0], b4 = p[1], c4 = p[2], d4 = p[3];
    float x[16] = {a.x, a.y, a.z, a.w,  b4.x, b4.y, b4.z, b4.w,
                   c4.x, c4.y, c4.z, c4.w, d4.x, d4.y, d4.z, d4.w};

    float del[16];
#pragma unroll
    for (int i = 0; i < 16; i++) del[i] = 0.f;

    auto clause2 = [&](int ia, int ib, float w) {
        float s1 = 1.f / (1.f + __expf(-(x[ia] + x[ib])));
        float s0 = 1.f - s1;
        del[ia] -= w * s0;
        del[ib] += w * s1;
    };
    auto clause3 = [&](int ia, int ib, int ic, float w) {
        float e0 = __expf(-x[ia]), e1 = __expf(x[ib]), e2 = __expf(x[ic]);
        float inv = __fdividef(w, e0 + e1 + e2);
        del[ia] -= inv * e0;
        del[ib] += inv * e1;
        del[ic] += inv * e2;
    };

    clause2(0, 1,       __ldg(uw + 0));
    clause2(1, 2,       __ldg(uw + 1));
    clause3(2, 3, 4,    __ldg(uw + 2));
    clause2(4, 5,       __ldg(uw + 3));
    clause3(6, 7, 8,    __ldg(uw + 4));
    clause2(8, 9,       __ldg(uw + 5));
    clause3(10, 11, 12, __ldg(uw + 6));
    clause3(13, 14, 15, __ldg(uw + 7));

    float u[16];
#pragma unroll
    for (int i = 0; i < 16; i++) u[i] = x[i] + del[i];

    float4* o = reinterpret_cast<float4*>(up_out + (size_t)node * 16);
    o[0] = make_float4(u[0],  u[1],  u[2],  u[3]);
    o[1] = make_float4(u[4],  u[5],  u[6],  u[7]);
    o[2] = make_float4(u[8],  u[9],  u[10], u[11]);
    o[3] = make_float4(u[12], u[13], u[14], u[15]);

    reinterpret_cast<float4*>(g_u4)[node] = make_float4(u[0], u[1], u[2], u[3]);
}

__device__ __forceinline__ void red_add_v4(float* ptr, float a, float b,
                                           float c, float d)
{
    asm volatile("red.global.add.v4.f32 [%0], {%1, %2, %3, %4};"
                 :: "l"(ptr), "f"(a), "f"(b), "f"(c), "f"(d)
                 : "memory");
}

// Per-edge core: given gathered u1/u2, binary row, weights -> REDG + bp value
__device__ __forceinline__ float4 edge_core(float4 u1, float4 u2, float4 bv,
                                            const float wv[4],
                                            float* __restrict__ up1,
                                            float* __restrict__ up2)
{
    float b[4]  = {bv.x, bv.y, bv.z, bv.w};
    float a1[4] = {u1.x, u1.y, u1.z, u1.w};
    float a2[4] = {u2.x, u2.y, u2.z, u2.w};

    float du1[4], du2[4], bpv[4];
#pragma unroll
    for (int i = 0; i < 4; i++) {
        float e0 = __expf(-a1[i]), e1 = __expf(-b[i]), e2 = __expf(a2[i]);
        float inv = __fdividef(wv[i], e0 + e1 + e2);
        du1[i] = -inv * e0;
        du2[i] =  inv * e2;
        bpv[i] = b[i] - inv * e1;
    }
    red_add_v4(up1, du1[0], du1[1], du1[2], du1[3]);
    red_add_v4(up2, du2[0], du2[1], du2[2], du2[3]);
    return make_float4(bpv[0], bpv[1], bpv[2], bpv[3]);
}

__global__ __launch_bounds__(256)
void binary_kernel(const float* __restrict__ binary,
                   const int* __restrict__ index1,
                   const int* __restrict__ index2,
                   const float* __restrict__ bw,
                   float* __restrict__ up_out,
                   float* __restrict__ bp_out,
                   int n_edges)
{
    const int base = blockIdx.x * (blockDim.x * 2) + threadIdx.x;
    const int eA = base;
    const int eB = base + blockDim.x;

    float wv[4] = {__ldg(bw + 0), __ldg(bw + 1), __ldg(bw + 2), __ldg(bw + 3)};

    if (eB < n_edges) {
        // fast path: both edges valid. Batch all loads for MLP.
        int i1A = index1[eA], i1B = index1[eB];
        int i2A = index2[eA], i2B = index2[eB];

        float4 u1A = reinterpret_cast<const float4*>(g_u4)[i1A];
        float4 u2A = reinterpret_cast<const float4*>(g_u4)[i2A];
        float4 u1B = reinterpret_cast<const float4*>(g_u4)[i1B];
        float4 u2B = reinterpret_cast<const float4*>(g_u4)[i2B];

        float4 bvA = reinterpret_cast<const float4*>(binary)[eA];
        float4 bvB = reinterpret_cast<const float4*>(binary)[eB];

        float4 bpA = edge_core(u1A, u2A, bvA, wv,
                               up_out + (size_t)i1A * 16,
                               up_out + (size_t)i2A * 16);
        float4 bpB = edge_core(u1B, u2B, bvB, wv,
                               up_out + (size_t)i1B * 16,
                               up_out + (size_t)i2B * 16);

        reinterpret_cast<float4*>(bp_out)[eA] = bpA;
        reinterpret_cast<float4*>(bp_out)[eB] = bpB;
    } else if (eA < n_edges) {
        int i1A = index1[eA];
        int i2A = index2[eA];
        float4 u1A = reinterpret_cast<const float4*>(g_u4)[i1A];
        float4 u2A = reinterpret_cast<const float4*>(g_u4)[i2A];
        float4 bvA = reinterpret_cast<const float4*>(binary)[eA];
        float4 bpA = edge_core(u1A, u2A, bvA, wv,
                               up_out + (size_t)i1A * 16,
                               up_out + (size_t)i2A * 16);
        reinterpret_cast<float4*>(bp_out)[eA] = bpA;
    }
}

extern "C" void kernel_launch(void* const* d_in, const int* in_sizes, int n_in,
                              void* d_out, int out_size)
{
    const float* unary   = (const float*)d_in[0];
    const float* binary  = (const float*)d_in[1];
    const int*   index1  = (const int*)d_in[2];
    const int*   index2  = (const int*)d_in[3];
    const float* uw      = (const float*)d_in[4];
    const float* bw      = (const float*)d_in[5];

    int n_nodes = in_sizes[0] / 16;
    int n_edges = in_sizes[1] / 4;

    float* up = (float*)d_out;
    float* bp = up + (size_t)n_nodes * 16;

    unary_kernel<<<(n_nodes + 255) / 256, 256>>>(unary, uw, up, n_nodes);

    int edges_per_block = 256 * 2;
    binary_kernel<<<(n_edges + edges_per_block - 1) / edges_per_block, 256>>>(
        binary, index1, index2, bw, up, bp, n_edges);
}